// round 5
// baseline (speedup 1.0000x reference)
#include <cuda_runtime.h>
#include <cstdint>

// conv_layer_65000035058096
// out[b,v,o] = sum_j sum_k x[b, nb[v*7+j], k] * W[o, j*64+k] + bias[o]
// GEMM M=2*163842, K=448, N=64, gathered A. fp32 via fma.rn.f32x2.
//
// R5: o-paired f32x2 accumulators (W naturally packed, NO smem duplication),
// A scalar + MOV-dup. Thread tile 8v x 8o -> bytes/thread/kk = 64 B, balanced
// against fma (16 LDS wf == 16 fma SM-cyc per warp,kk). Crossbar model:
// returned bytes count replication (lesson from R2/R3/R4 ratios).

#define V_TOT 163842
#define NBATCH 2
#define TILE_V 256
#define KCH 16
#define NCH 28            // 448/16
#define SA_W 258          // As row stride in WORDS (mod 8 == 2 -> STS + LDS conflict-free)
#define SW4 33            // Ws4 row stride in float4

// packed W: g_Wp4[kp*32+op] = (W[2op][2kp],W[2op+1][2kp],W[2op][2kp+1],W[2op+1][2kp+1])
// (W row-major (64,448): W[o][k] = W[o*448+k])
__device__ float4 g_Wp4[224 * 32];

__global__ void pack_W_kernel(const float* __restrict__ W) {
    int idx = blockIdx.x * blockDim.x + threadIdx.x;
    if (idx < 224 * 32) {
        int kp = idx >> 5, op = idx & 31;
        int o0 = 2 * op, o1 = 2 * op + 1, k0 = 2 * kp, k1 = 2 * kp + 1;
        g_Wp4[idx] = make_float4(W[o0 * 448 + k0], W[o1 * 448 + k0],
                                 W[o0 * 448 + k1], W[o1 * 448 + k1]);
    }
}

__global__ __launch_bounds__(256, 2)
void sconv_kernel(const float* __restrict__ x,
                  const int* __restrict__ nb,
                  const float* __restrict__ bias,
                  float* __restrict__ out) {
    __shared__ float  As[KCH * SA_W];      // 16512 B, transposed A: As[kk][v]
    __shared__ float4 Ws4[8 * SW4];        // 4224 B, packed W pairs
    __shared__ int    nbs[TILE_V * 7];     // 7168 B

    const int t    = threadIdx.x;
    const int lane = t & 31;
    const int warp = t >> 5;
    const int vg   = lane & 3;          // vertex subgroup
    const int ogl  = lane >> 2;         // output group (8 outputs)
    const int wv   = warp << 5;         // warp vertex base (32 v per warp)
    const int batch = blockIdx.y;
    const int v0    = blockIdx.x * TILE_V;
    const long long xbase = (long long)batch * V_TOT;

    // ---- stage neighbor indices
#pragma unroll
    for (int i = 0; i < 7; ++i) {
        int idx = t + (i << 8);
        int g = v0 * 7 + idx;
        nbs[idx] = (g < V_TOT * 7) ? nb[g] : 0;
    }
    __syncthreads();

    // acc[vl][q]: f32x2 over outputs (ogl*8+2q, +1) for local vertex vl=2m+e
    unsigned long long acc[8][4];
#pragma unroll
    for (int v = 0; v < 8; ++v)
#pragma unroll
        for (int q = 0; q < 4; ++q) acc[v][q] = 0ull;

    const int vS = t >> 2;     // staging vertex 0..63 (+64i)
    const int qS = t & 3;      // staging k-quad

    for (int c = 0; c < NCH; ++c) {
        const int j  = c >> 2;
        const int kb = (c & 3) << 4;
        __syncthreads();   // smem reusable

        // ---- stage W chunk: straight copy of 256 float4 (1 per thread)
        {
            const int kpg = j * 32 + ((c & 3) << 3);   // global k-pair base
            Ws4[(t >> 5) * SW4 + (t & 31)] = g_Wp4[(kpg + (t >> 5)) * 32 + (t & 31)];
        }

        // ---- stage A transposed: As[kk][v] (gather float4 per (v,k-quad))
#pragma unroll
        for (int i = 0; i < 4; ++i) {
            int v  = vS + (i << 6);
            int sv = (v0 + v < V_TOT) ? v : 0;
            int r  = nbs[sv * 7 + j];
            const float4 d = *reinterpret_cast<const float4*>(
                x + ((xbase + r) << 6) + kb + (qS << 2));
            float* a = As + (qS << 2) * SA_W + v;
            a[0 * SA_W] = d.x; a[1 * SA_W] = d.y;
            a[2 * SA_W] = d.z; a[3 * SA_W] = d.w;
        }
        __syncthreads();

        // ---- compute: per k-pair: 4 w-LDS.128 + 8 a-LDS.64 + 16 MOV + 64 FFMA2
        const float* aW = As + wv + (vg << 1);
#pragma unroll
        for (int kp = 0; kp < 8; ++kp) {
            ulonglong2 w[4];
#pragma unroll
            for (int q = 0; q < 4; ++q)
                w[q] = *reinterpret_cast<const ulonglong2*>(
                    Ws4 + kp * SW4 + (ogl << 2) + q);

            const float* ap = aW + (kp << 1) * SA_W;
#pragma unroll
            for (int m = 0; m < 4; ++m) {
                float2 a0 = *reinterpret_cast<const float2*>(ap + (m << 3));
                float2 a1 = *reinterpret_cast<const float2*>(ap + SA_W + (m << 3));
                unsigned long long d;
                asm("mov.b64 %0,{%1,%1};" : "=l"(d) : "f"(a0.x));
#pragma unroll
                for (int q = 0; q < 4; ++q)
                    asm("fma.rn.f32x2 %0, %1, %2, %0;"
                        : "+l"(acc[2 * m][q]) : "l"(d), "l"(w[q].x));
                asm("mov.b64 %0,{%1,%1};" : "=l"(d) : "f"(a1.x));
#pragma unroll
                for (int q = 0; q < 4; ++q)
                    asm("fma.rn.f32x2 %0, %1, %2, %0;"
                        : "+l"(acc[2 * m][q]) : "l"(d), "l"(w[q].y));
                asm("mov.b64 %0,{%1,%1};" : "=l"(d) : "f"(a0.y));
#pragma unroll
                for (int q = 0; q < 4; ++q)
                    asm("fma.rn.f32x2 %0, %1, %2, %0;"
                        : "+l"(acc[2 * m + 1][q]) : "l"(d), "l"(w[q].x));
                asm("mov.b64 %0,{%1,%1};" : "=l"(d) : "f"(a1.y));
#pragma unroll
                for (int q = 0; q < 4; ++q)
                    asm("fma.rn.f32x2 %0, %1, %2, %0;"
                        : "+l"(acc[2 * m + 1][q]) : "l"(d), "l"(w[q].y));
            }
        }
    }

    // ---- epilogue: unpack, +bias, 2x STG.128 per vertex
    const int ob = ogl << 3;
    const float4 b0 = *reinterpret_cast<const float4*>(bias + ob);
    const float4 b1 = *reinterpret_cast<const float4*>(bias + ob + 4);

#pragma unroll
    for (int vl = 0; vl < 8; ++vl) {
        const int gv = v0 + wv + (vg << 1) + ((vl >> 1) << 3) + (vl & 1);
        if (gv < V_TOT) {
            float f[8];
#pragma unroll
            for (int q = 0; q < 4; ++q)
                asm("mov.b64 {%0,%1}, %2;"
                    : "=f"(f[2 * q]), "=f"(f[2 * q + 1]) : "l"(acc[vl][q]));
            float* orow = out + ((xbase + gv) << 6) + ob;
            *reinterpret_cast<float4*>(orow) =
                make_float4(f[0] + b0.x, f[1] + b0.y, f[2] + b0.z, f[3] + b0.w);
            *reinterpret_cast<float4*>(orow + 4) =
                make_float4(f[4] + b1.x, f[5] + b1.y, f[6] + b1.z, f[7] + b1.w);
        }
    }
}

extern "C" void kernel_launch(void* const* d_in, const int* in_sizes, int n_in,
                              void* d_out, int out_size) {
    const float* x   = (const float*)d_in[0];   // (2, V, 64) f32
    const int*   nb  = (const int*)d_in[1];     // (V*7,) i32
    const float* W   = (const float*)d_in[2];   // (64, 448) f32
    const float* b   = (const float*)d_in[3];   // (64,) f32
    float*       out = (float*)d_out;           // (2, V, 64) f32

    pack_W_kernel<<<(224 * 32 + 255) / 256, 256>>>(W);

    dim3 grid((V_TOT + TILE_V - 1) / TILE_V, NBATCH);
    sconv_kernel<<<grid, 256>>>(x, nb, b, out);
}

// round 6
// speedup vs baseline: 1.1728x; 1.1728x over previous
#include <cuda_runtime.h>
#include <cstdint>

// conv_layer_65000035058096
// out[b,v,o] = sum_j sum_k x[b, nb[v*7+j], k] * W[o, j*64+k] + bias[o]
// GEMM M=2*163842, K=448, N=64, gathered A. fp32 via fma.rn.f32x2.
//
// R6: R5's balanced 8v x 8o o-paired FFMA2 loop + cp.async double-buffered
// staging (v-major A rows -> direct global->shared gather, no transpose STS),
// bank-perfect W slot permutation, neighbor-index register prefetch.

#define V_TOT 163842
#define NBATCH 2
#define TILE_V 256
#define KCH 16
#define NCH 28            // 448/16
#define SA 20             // As row stride in words (80 B: 16B-aligned, banks 0/8/16/24)

// packed W pairs: g_Wp4[kp*32+op] = (W[2op][2kp],W[2op+1][2kp],W[2op][2kp+1],W[2op+1][2kp+1])
__device__ float4 g_Wp4[224 * 32];

__global__ void pack_W_kernel(const float* __restrict__ W) {
    int idx = blockIdx.x * blockDim.x + threadIdx.x;
    if (idx < 224 * 32) {
        int kp = idx >> 5, op = idx & 31;
        int o0 = 2 * op, o1 = 2 * op + 1, k0 = 2 * kp, k1 = 2 * kp + 1;
        g_Wp4[idx] = make_float4(W[o0 * 448 + k0], W[o1 * 448 + k0],
                                 W[o0 * 448 + k1], W[o1 * 448 + k1]);
    }
}

__device__ __forceinline__ void cpa16(uint32_t dst, const void* src) {
    asm volatile("cp.async.cg.shared.global [%0], [%1], 16;"
                 :: "r"(dst), "l"(src) : "memory");
}
__device__ __forceinline__ uint32_t smem_u32(const void* p) {
    uint32_t a;
    asm("{ .reg .u64 t; cvta.to.shared.u64 t, %1; cvt.u32.u64 %0, t; }"
        : "=r"(a) : "l"(p));
    return a;
}

__global__ __launch_bounds__(256, 2)
void sconv_kernel(const float* __restrict__ x,
                  const int* __restrict__ nb,
                  const float* __restrict__ bias,
                  float* __restrict__ out) {
    __shared__ float  As[2][TILE_V * SA];   // 2 x 20480 B, v-major: As[v][kk]
    __shared__ float4 Ws4[2][8 * 32];       // 2 x 4096 B, slot = kp*32 + q*8 + ogl

    const int t    = threadIdx.x;
    const int lane = t & 31;
    const int warp = t >> 5;
    const int vg   = lane & 3;
    const int ogl  = lane >> 2;
    const int wv   = warp << 5;
    const int batch = blockIdx.y;
    const int v0    = blockIdx.x * TILE_V;
    const long long xbase = (long long)batch * V_TOT;

    // staging mapping
    const int vS = t >> 2;        // 0..63 (+64*i)
    const int qS = t & 3;         // 16B chunk within the 16-k row
    const int kpr = t >> 5;       // W staging k-pair row 0..7
    const int pos = t & 31;       // W slot within row; op = (pos&7)*4 + (pos>>3)
    const int opS = ((pos & 7) << 2) + (pos >> 3);

    // clamped staging vertices (OOB tail reuses vertex 0..3 rows; discarded later)
    int svv[4];
#pragma unroll
    for (int i = 0; i < 4; ++i) {
        int v = vS + (i << 6);
        svv[i] = (v0 + v < V_TOT) ? v : 0;
    }

    uint32_t asb[2] = { smem_u32(&As[0][0]), smem_u32(&As[1][0]) };
    uint32_t wsb[2] = { smem_u32(&Ws4[0][0]), smem_u32(&Ws4[1][0]) };

    unsigned long long acc[8][4];
#pragma unroll
    for (int v = 0; v < 8; ++v)
#pragma unroll
        for (int q = 0; q < 4; ++q) acc[v][q] = 0ull;

    // rn invariant: holds neighbor indices for the NEXT chunk to stage
    int rn[4];
#pragma unroll
    for (int i = 0; i < 4; ++i) rn[i] = nb[(v0 + svv[i]) * 7 + 0];

    // ---- prologue: stage chunk 0 into buf 0
    {
        const int kpg = 0;
#pragma unroll
        for (int i = 0; i < 4; ++i) {
            int v = vS + (i << 6);
            cpa16(asb[0] + (v * SA + (qS << 2)) * 4,
                  x + ((xbase + rn[i]) << 6) + (qS << 2));
        }
        cpa16(wsb[0] + ((kpr << 5) + pos) * 16, g_Wp4 + (kpg + kpr) * 32 + opS);
        asm volatile("cp.async.commit_group;" ::: "memory");
    }
    // rn already valid for chunk 1 (j(1)==0)

    for (int c = 0; c < NCH; ++c) {
        const int buf = c & 1;

        if (c + 1 < NCH) {
            const int cn  = c + 1;
            const int jn  = cn >> 2;
            const int kbn = (cn & 3) << 4;
            const int bn  = cn & 1;
            const int kpg = jn * 32 + ((cn & 3) << 3);
#pragma unroll
            for (int i = 0; i < 4; ++i) {
                int v = vS + (i << 6);
                cpa16(asb[bn] + (v * SA + (qS << 2)) * 4,
                      x + ((xbase + rn[i]) << 6) + kbn + (qS << 2));
            }
            cpa16(wsb[bn] + ((kpr << 5) + pos) * 16, g_Wp4 + (kpg + kpr) * 32 + opS);
            asm volatile("cp.async.commit_group;" ::: "memory");

            // prefetch neighbor indices for chunk c+2 (hidden under compute)
            if (c + 2 < NCH) {
                const int j2 = (c + 2) >> 2;
#pragma unroll
                for (int i = 0; i < 4; ++i)
                    rn[i] = nb[(v0 + svv[i]) * 7 + j2];
            }
            asm volatile("cp.async.wait_group 1;" ::: "memory");
        } else {
            asm volatile("cp.async.wait_group 0;" ::: "memory");
        }
        __syncthreads();

        // ---- compute on buf: per kp: 4 w-LDS.128 + 8 a-LDS.64 + 16 MOVs + 64 FFMA2
        const float*  aB = &As[buf][(wv + (vg << 1)) * SA];
        const float4* wB = &Ws4[buf][0];
#pragma unroll
        for (int kp = 0; kp < 8; ++kp) {
            ulonglong2 w[4];
#pragma unroll
            for (int q = 0; q < 4; ++q)
                w[q] = *reinterpret_cast<const ulonglong2*>(
                    wB + (kp << 5) + (q << 3) + ogl);
#pragma unroll
            for (int i = 0; i < 4; ++i) {
#pragma unroll
                for (int e = 0; e < 2; ++e) {
                    float2 a = *reinterpret_cast<const float2*>(
                        aB + ((i << 3) + e) * SA + (kp << 1));
                    unsigned long long d;
                    asm("mov.b64 %0,{%1,%1};" : "=l"(d) : "f"(a.x));
#pragma unroll
                    for (int q = 0; q < 4; ++q)
                        asm("fma.rn.f32x2 %0, %1, %2, %0;"
                            : "+l"(acc[2 * i + e][q]) : "l"(d), "l"(w[q].x));
                    asm("mov.b64 %0,{%1,%1};" : "=l"(d) : "f"(a.y));
#pragma unroll
                    for (int q = 0; q < 4; ++q)
                        asm("fma.rn.f32x2 %0, %1, %2, %0;"
                            : "+l"(acc[2 * i + e][q]) : "l"(d), "l"(w[q].y));
                }
            }
        }
        __syncthreads();   // compute done before this buffer is re-staged
    }

    // ---- epilogue: unpack, +bias, 2x STG.128 per vertex
    const int ob = ogl << 3;
    const float4 b0 = *reinterpret_cast<const float4*>(bias + ob);
    const float4 b1 = *reinterpret_cast<const float4*>(bias + ob + 4);

#pragma unroll
    for (int v8 = 0; v8 < 8; ++v8) {
        const int gv = v0 + wv + ((v8 >> 1) << 3) + (vg << 1) + (v8 & 1);
        if (gv < V_TOT) {
            float f[8];
#pragma unroll
            for (int q = 0; q < 4; ++q)
                asm("mov.b64 {%0,%1}, %2;"
                    : "=f"(f[2 * q]), "=f"(f[2 * q + 1]) : "l"(acc[v8][q]));
            float* orow = out + ((xbase + gv) << 6) + ob;
            *reinterpret_cast<float4*>(orow) =
                make_float4(f[0] + b0.x, f[1] + b0.y, f[2] + b0.z, f[3] + b0.w);
            *reinterpret_cast<float4*>(orow + 4) =
                make_float4(f[4] + b1.x, f[5] + b1.y, f[6] + b1.z, f[7] + b1.w);
        }
    }
}

extern "C" void kernel_launch(void* const* d_in, const int* in_sizes, int n_in,
                              void* d_out, int out_size) {
    const float* x   = (const float*)d_in[0];   // (2, V, 64) f32
    const int*   nb  = (const int*)d_in[1];     // (V*7,) i32
    const float* W   = (const float*)d_in[2];   // (64, 448) f32
    const float* b   = (const float*)d_in[3];   // (64,) f32
    float*       out = (float*)d_out;           // (2, V, 64) f32

    pack_W_kernel<<<(224 * 32 + 255) / 256, 256>>>(W);

    dim3 grid((V_TOT + TILE_V - 1) / TILE_V, NBATCH);
    sconv_kernel<<<grid, 256>>>(x, nb, b, out);
}

// round 9
// speedup vs baseline: 2.2525x; 1.9207x over previous
#include <cuda_runtime.h>
#include <cuda_bf16.h>
#include <cstdint>

// conv_layer_65000035058096 — 3xBF16 mma.sync gather-GEMM (baseline PTX)
// out[b,v,o] = sum_k xg[v,k]*W[o,k] + bias[o]; M=2*163842, K=448, N=64.
// D = xh*wh + xh*wl + xl*wh  (bf16 hi/lo split, fp32 accum, err ~2^-18)

#define V_TOT 163842
#define NCH 28            // k-steps of 16
#define SA 20             // As row stride in words (16 data + 4 pad) -> conflict-free frags

// B fragments, mma m16n8k16 register layout, hi/lo packed:
// g_Bf[(s*8+nb)*32 + lane] = {bh0, bh1, bl0, bl1}
__device__ uint4 g_Bf[NCH * 8 * 32];

__device__ __forceinline__ uint32_t pack_bf16_hi_lo(float hi_elem, float lo_elem) {
    // returns (bf16(hi_elem) << 16) | bf16(lo_elem)
    uint32_t r;
    asm("cvt.rn.bf16x2.f32 %0, %1, %2;" : "=r"(r) : "f"(hi_elem), "f"(lo_elem));
    return r;
}

__global__ void pack_B_kernel(const float* __restrict__ W) {
    int idx = blockIdx.x * blockDim.x + threadIdx.x;   // 28*8*32 = 7168
    if (idx < NCH * 8 * 32) {
        int l = idx & 31, nb = (idx >> 5) & 7, s = idx >> 8;
        int g = l >> 2, tig = l & 3;
        int o = nb * 8 + g;
        const float* wr = W + o * 448 + s * 16 + 2 * tig;
        float v[4] = { wr[0], wr[1], wr[8], wr[9] };   // k: 2tig,2tig+1,2tig+8,2tig+9
        float h[4], lo[4];
#pragma unroll
        for (int i = 0; i < 4; ++i) {
            __nv_bfloat16 hb = __float2bfloat16_rn(v[i]);
            h[i] = __bfloat162float(hb);
            lo[i] = v[i] - h[i];
        }
        uint4 r;
        r.x = pack_bf16_hi_lo(h[1], h[0]);     // low half = k even
        r.y = pack_bf16_hi_lo(h[3], h[2]);
        r.z = pack_bf16_hi_lo(lo[1], lo[0]);
        r.w = pack_bf16_hi_lo(lo[3], lo[2]);
        g_Bf[idx] = r;
    }
}

__device__ __forceinline__ void cpa16(uint32_t dst, const void* src) {
    asm volatile("cp.async.cg.shared.global [%0], [%1], 16;" :: "r"(dst), "l"(src) : "memory");
}
__device__ __forceinline__ uint32_t smem_u32(const void* p) {
    uint32_t a;
    asm("{ .reg .u64 t; cvta.to.shared.u64 t, %1; cvt.u32.u64 %0, t; }" : "=r"(a) : "l"(p));
    return a;
}
__device__ __forceinline__ void cvt_pair(float2 p, uint32_t& hi2, uint32_t& lo2) {
    uint32_t h;
    asm("cvt.rn.bf16x2.f32 %0, %1, %2;" : "=r"(h) : "f"(p.y), "f"(p.x));
    float hx = __uint_as_float(h << 16);
    float hy = __uint_as_float(h & 0xFFFF0000u);
    float lx = p.x - hx, ly = p.y - hy;
    uint32_t l;
    asm("cvt.rn.bf16x2.f32 %0, %1, %2;" : "=r"(l) : "f"(ly), "f"(lx));
    hi2 = h; lo2 = l;
}
#define MMA(c, a, b0, b1) asm volatile( \
    "mma.sync.aligned.m16n8k16.row.col.f32.bf16.bf16.f32 " \
    "{%0,%1,%2,%3}, {%4,%5,%6,%7}, {%8,%9}, {%0,%1,%2,%3};" \
    : "+f"((c)[0]), "+f"((c)[1]), "+f"((c)[2]), "+f"((c)[3]) \
    : "r"((a)[0]), "r"((a)[1]), "r"((a)[2]), "r"((a)[3]), "r"(b0), "r"(b1))

__global__ __launch_bounds__(256, 2)
void sconv_bf16(const float* __restrict__ x,
                const int* __restrict__ nb,
                const float* __restrict__ bias,
                float* __restrict__ out) {
    __shared__ float As[2][128 * SA];   // 2 x 10240 B, gathered fp32 rows
    __shared__ uint4 Bs[2][8 * 32];     // 2 x 4096 B, B fragments
    __shared__ int   nbs[896];          // [j][row]

    const int t    = threadIdx.x;
    const int lane = t & 31;
    const int w    = t >> 5;
    const int g    = lane >> 2;
    const int tig  = lane & 3;
    const int wv   = w << 4;            // warp vertex base (16 v per warp)
    const int batch = blockIdx.y;
    const int v0    = blockIdx.x * 128;
    const long long xbase = (long long)batch * V_TOT;

    // ---- stage neighbor indices: nbs[j*128 + r]
#pragma unroll
    for (int i = 0; i < 4; ++i) {
        int idx = t + (i << 8);
        if (idx < 896) {
            int r = idx & 127, j = idx >> 7;
            int vv = v0 + r; if (vv >= V_TOT) vv = V_TOT - 1;
            nbs[idx] = nb[vv * 7 + j];
        }
    }
    __syncthreads();

    uint32_t asb[2] = { smem_u32(&As[0][0]), smem_u32(&As[1][0]) };
    uint32_t bsb[2] = { smem_u32(&Bs[0][0]), smem_u32(&Bs[1][0]) };

    float acc[8][4];
#pragma unroll
    for (int n = 0; n < 8; ++n)
#pragma unroll
        for (int e = 0; e < 4; ++e) acc[n][e] = 0.0f;

    // ---- staging mapping: 512 (row,quad) tasks over 256 threads x 2
    const int rS = t >> 1;              // row 0..127 (fixed per thread)
    const int qS0 = (t & 1) << 1;       // quads {0,1} (even t) / {2,3} (odd t)

    // prologue: stage chunk 0
    {
#pragma unroll
        for (int i = 0; i < 2; ++i) {
            int q = qS0 + i;
            const float* src = x + ((xbase + nbs[rS]) << 6) + (q << 2);
            cpa16(asb[0] + (rS * SA + (q << 2)) * 4, src);
        }
        cpa16(bsb[0] + t * 16, (const char*)g_Bf + t * 16);
        asm volatile("cp.async.commit_group;" ::: "memory");
    }

    for (int c = 0; c < NCH; ++c) {
        const int buf = c & 1;

        if (c + 1 < NCH) {
            const int cn  = c + 1;
            const int j   = cn >> 2;
            const int kb  = (cn & 3) << 4;
            const int bn  = cn & 1;
            const int row = nbs[j * 128 + rS];
#pragma unroll
            for (int i = 0; i < 2; ++i) {
                int q = qS0 + i;
                const float* src = x + ((xbase + row) << 6) + kb + (q << 2);
                cpa16(asb[bn] + (rS * SA + (q << 2)) * 4, src);
            }
            cpa16(bsb[bn] + t * 16, (const char*)g_Bf + cn * 4096 + t * 16);
            asm volatile("cp.async.commit_group;" ::: "memory");
            asm volatile("cp.async.wait_group 1;" ::: "memory");
        } else {
            asm volatile("cp.async.wait_group 0;" ::: "memory");
        }
        __syncthreads();

        // ---- compute chunk c
        const float* aB = &As[buf][0];
        const int r0 = (wv + g) * SA;
        const int r1 = (wv + g + 8) * SA;
        float2 p00 = *reinterpret_cast<const float2*>(aB + r0 + 2 * tig);
        float2 p10 = *reinterpret_cast<const float2*>(aB + r1 + 2 * tig);
        float2 p01 = *reinterpret_cast<const float2*>(aB + r0 + 2 * tig + 8);
        float2 p11 = *reinterpret_cast<const float2*>(aB + r1 + 2 * tig + 8);
        uint32_t ah[4], al[4];
        cvt_pair(p00, ah[0], al[0]);
        cvt_pair(p10, ah[1], al[1]);
        cvt_pair(p01, ah[2], al[2]);
        cvt_pair(p11, ah[3], al[3]);

        const uint4* bB = &Bs[buf][0];
#pragma unroll
        for (int nblk = 0; nblk < 8; ++nblk) {
            uint4 bf = bB[(nblk << 5) + lane];
            MMA(acc[nblk], ah, bf.x, bf.y);   // xh * wh
            MMA(acc[nblk], ah, bf.z, bf.w);   // xh * wl
            MMA(acc[nblk], al, bf.x, bf.y);   // xl * wh
        }
        __syncthreads();   // done reading buf before it is re-staged
    }

    // ---- epilogue: D frag -> global (+bias). c0,c1: row g, cols 2tig,+1; c2,c3: row g+8
    const int vr0 = v0 + wv + g;
    const int vr1 = vr0 + 8;
#pragma unroll
    for (int nblk = 0; nblk < 8; ++nblk) {
        const int n = (nblk << 3) + 2 * tig;
        const float2 b2 = *reinterpret_cast<const float2*>(bias + n);
        if (vr0 < V_TOT)
            *reinterpret_cast<float2*>(out + ((xbase + vr0) << 6) + n) =
                make_float2(acc[nblk][0] + b2.x, acc[nblk][1] + b2.y);
        if (vr1 < V_TOT)
            *reinterpret_cast<float2*>(out + ((xbase + vr1) << 6) + n) =
                make_float2(acc[nblk][2] + b2.x, acc[nblk][3] + b2.y);
    }
}

extern "C" void kernel_launch(void* const* d_in, const int* in_sizes, int n_in,
                              void* d_out, int out_size) {
    const float* x   = (const float*)d_in[0];   // (2, V, 64) f32
    const int*   nbi = (const int*)d_in[1];     // (V*7,) i32
    const float* W   = (const float*)d_in[2];   // (64, 448) f32
    const float* b   = (const float*)d_in[3];   // (64,) f32
    float*       out = (float*)d_out;           // (2, V, 64) f32

    pack_B_kernel<<<(NCH * 8 * 32 + 255) / 256, 256>>>(W);

    dim3 grid((V_TOT + 127) / 128, 2);
    sconv_bf16<<<grid, 256>>>(x, nbi, b, out);
}